// round 16
// baseline (speedup 1.0000x reference)
#include <cuda_runtime.h>
#include <math.h>

#define CDIV(a,b) (((a)+(b)-1)/(b))

static constexpr int B  = 32;
static constexpr int KN = 16;
static constexpr int N0 = 2048, N1 = 512, N2 = 128;

// ---------------- scratch ----------------
static constexpr size_t OFF_G1  = 0;                                  // B*N0*32
static constexpr size_t OFF_H1  = OFF_G1  + (size_t)B*N0*32;
static constexpr size_t OFF_M1  = OFF_H1  + (size_t)B*N0*32;
static constexpr size_t OFF_MN1 = OFF_M1  + (size_t)B*N0*32;
static constexpr size_t OFF_F1  = OFF_MN1 + (size_t)B*N0*32;          // B*32*N0
static constexpr size_t OFF_CQ1 = OFF_F1  + (size_t)B*32*N0;          // B*3*N1
static constexpr size_t OFF_FQ1 = OFF_CQ1 + (size_t)B*3*N1;           // B*32*N1
static constexpr size_t OFF_G2  = OFF_FQ1 + (size_t)B*32*N1;          // B*N0*64
static constexpr size_t OFF_H2  = OFF_G2  + (size_t)B*N0*64;          // B*N1*64
static constexpr size_t OFF_M2  = OFF_H2  + (size_t)B*N1*64;
static constexpr size_t OFF_MN2 = OFF_M2  + (size_t)B*N1*64;
static constexpr size_t OFF_F2  = OFF_MN2 + (size_t)B*N1*64;          // B*64*N1
static constexpr size_t OFF_G3  = OFF_F2  + (size_t)B*64*N1;
static constexpr size_t OFF_H3  = OFF_G3  + (size_t)B*N1*64;
static constexpr size_t OFF_M3  = OFF_H3  + (size_t)B*N1*64;
static constexpr size_t OFF_MN3 = OFF_M3  + (size_t)B*N1*64;
static constexpr size_t OFF_F3  = OFF_MN3 + (size_t)B*N1*64;          // B*64*N1
static constexpr size_t OFF_FQ3 = OFF_F3  + (size_t)B*64*N1;          // B*64*N2
static constexpr size_t OFF_G4  = OFF_FQ3 + (size_t)B*64*N2;          // B*N1*128
static constexpr size_t OFF_H4  = OFF_G4  + (size_t)B*N1*128;         // B*N2*128
static constexpr size_t OFF_M4  = OFF_H4  + (size_t)B*N2*128;
static constexpr size_t OFF_MN4 = OFF_M4  + (size_t)B*N2*128;
static constexpr size_t FBUF_TOTAL = OFF_MN4 + (size_t)B*N2*128;

__device__ float d_fbuf[FBUF_TOTAL];

static constexpr size_t IOFF_IDX1 = 0;
static constexpr size_t IOFF_FPS1 = IOFF_IDX1 + (size_t)B*N0*KN;
static constexpr size_t IOFF_IDX2 = IOFF_FPS1 + (size_t)B*N1;
static constexpr size_t IOFF_IDX3 = IOFF_IDX2 + (size_t)B*N1*KN;
static constexpr size_t IOFF_FPS2 = IOFF_IDX3 + (size_t)B*N1*KN;
static constexpr size_t IOFF_IDX4 = IOFF_FPS2 + (size_t)B*N2;
static constexpr size_t IBUF_TOTAL = IOFF_IDX4 + (size_t)B*N2*KN;

__device__ int d_ibuf[IBUF_TOTAL];
__device__ double d_statsbuf[4 * B * 4 * 2];   // [layer][b][group][{sum,sumsq}]
__device__ int d_cntbuf[4 * B];                // last-block counters per stage/batch

// ---------------- device helpers ----------------

// Warp-cooperative KNN, 512-thread blocks, 16 queries/block (proven R12/R14).
__device__ __forceinline__ void dev_knn(int NK, const float* __restrict__ cq,
                                        const float* __restrict__ ck,
                                        int Nq, int* __restrict__ idx_out,
                                        int qblk, int b, char* sraw) {
    float4* skey = (float4*)sraw;
    const float* ckb = ck + (size_t)b*3*NK;
    for (int j = threadIdx.x; j < NK; j += 512) {
        float kx = ckb[j], ky = ckb[NK + j], kz = ckb[2*NK + j];
        skey[j] = make_float4(-2.f*kx, -2.f*ky, -2.f*kz, kx*kx + ky*ky + kz*kz);
    }
    __syncthreads();
    int w = threadIdx.x >> 5, lane = threadIdx.x & 31;
    int q = qblk * 16 + w;
    const float* cqb = cq + (size_t)b*3*Nq;
    float qx = cqb[q], qy = cqb[Nq + q], qz = cqb[2*Nq + q];

    float bd; int bj;
    {
        float4 kk = skey[lane];
        bd = fmaf(kk.x, qx, fmaf(kk.y, qy, fmaf(kk.z, qz, kk.w)));
        bj = lane;
#pragma unroll
        for (int k = 2; k <= 32; k <<= 1) {
#pragma unroll
            for (int s2 = k >> 1; s2 > 0; s2 >>= 1) {
                float pd = __shfl_xor_sync(0xffffffffu, bd, s2);
                int   pj = __shfl_xor_sync(0xffffffffu, bj, s2);
                bool asc    = ((lane & k)  == 0) || (k == 32);
                bool lower  = ((lane & s2) == 0);
                bool pLess  = (pd < bd) || (pd == bd && pj < bj);
                bool take   = ((asc == lower) == pLess);
                bd = take ? pd : bd;
                bj = take ? pj : bj;
            }
        }
    }
    float th = __shfl_sync(0xffffffffu, bd, 15);

    for (int j0 = 32; j0 < NK; j0 += 64) {
        float4 kkA = skey[j0 + lane];
        float dA = fmaf(kkA.x, qx, fmaf(kkA.y, qy, fmaf(kkA.z, qz, kkA.w)));
        unsigned hitsA = __ballot_sync(0xffffffffu, dA < th);
        bool hasB = (j0 + 32) < NK;
        float dB = 0.f;
        unsigned hitsB = 0;
        if (hasB) {
            float4 kkB = skey[j0 + 32 + lane];
            dB = fmaf(kkB.x, qx, fmaf(kkB.y, qy, fmaf(kkB.z, qz, kkB.w)));
            hitsB = __ballot_sync(0xffffffffu, dB < th);
        }
        while (hitsA) {
            int s = __ffs(hitsA) - 1;
            hitsA &= hitsA - 1;
            float dd = __shfl_sync(0xffffffffu, dA, s);
            if (dd < th) {
                int r = __popc(__ballot_sync(0xffffffffu, bd <= dd) & 0xFFFFu);
                float pd = __shfl_up_sync(0xffffffffu, bd, 1);
                int   pj = __shfl_up_sync(0xffffffffu, bj, 1);
                if (lane > r && lane < 16) { bd = pd; bj = pj; }
                if (lane == r)             { bd = dd; bj = j0 + s; }
                th = __shfl_sync(0xffffffffu, bd, 15);
            }
        }
        while (hitsB) {
            int s = __ffs(hitsB) - 1;
            hitsB &= hitsB - 1;
            float dd = __shfl_sync(0xffffffffu, dB, s);
            if (dd < th) {
                int r = __popc(__ballot_sync(0xffffffffu, bd <= dd) & 0xFFFFu);
                float pd = __shfl_up_sync(0xffffffffu, bd, 1);
                int   pj = __shfl_up_sync(0xffffffffu, bj, 1);
                if (lane > r && lane < 16) { bd = pd; bj = pj; }
                if (lane == r)             { bd = dd; bj = j0 + 32 + s; }
                th = __shfl_sync(0xffffffffu, bd, 15);
            }
        }
    }
    if (lane < 16) idx_out[((size_t)b*Nq + q)*KN + lane] = bj;
}

// FPS, 512 threads, one barrier/iter, packed-u64 block merge (proven).
template<int N, int S>
__device__ __forceinline__ void dev_fps(const float* __restrict__ coor,
                                        int* __restrict__ out, int b, char* sraw) {
    constexpr int BLK = 512, PPT = N / BLK, NW = BLK / 32;
    float* sx = (float*)sraw;
    float* sy = sx + N;
    float* sz = sy + N;
    unsigned long long* spk = (unsigned long long*)(sz + N);
    int t = threadIdx.x, lane = t & 31, w = t >> 5;
    const float* cb = coor + (size_t)b*3*N;

    float px[PPT], py[PPT], pz[PPT], dist[PPT];
#pragma unroll
    for (int p = 0; p < PPT; p++) {
        int i = t + p * BLK;
        float vx = cb[i], vy = cb[N + i], vz = cb[2*N + i];
        px[p] = vx; py[p] = vy; pz[p] = vz;
        sx[i] = vx; sy[i] = vy; sz[i] = vz;
        dist[p] = 1e10f;
    }
    __syncthreads();

    int last = 0;
    for (int s = 0; s < S; s++) {
        if (t == 0) out[(size_t)b*S + s] = last;
        float cx = sx[last], cy = sy[last], cz = sz[last];
        float bv = -1.0f; int bidx = 0;
#pragma unroll
        for (int p = 0; p < PPT; p++) {
            float dx = px[p]-cx, dy = py[p]-cy, dz = pz[p]-cz;
            float d = dx*dx + dy*dy + dz*dz;
            float nd = fminf(dist[p], d);
            dist[p] = nd;
            if (nd > bv) { bv = nd; bidx = t + p * BLK; }
        }
        unsigned bits = __float_as_uint(fmaxf(bv, 0.0f));
        unsigned m  = __reduce_max_sync(0xffffffffu, bits);
        unsigned ci = (bits == m) ? (unsigned)bidx : 0xffffffffu;
        unsigned mi = __reduce_min_sync(0xffffffffu, ci);
        int buf = (s & 1) * NW;
        if (lane == 0)
            spk[buf + w] = ((unsigned long long)m << 32) | (unsigned)(~mi);
        __syncthreads();
        unsigned long long best = spk[buf + 0];
#pragma unroll
        for (int i2 = 1; i2 < NW; i2++) {
            unsigned long long v = spk[buf + i2];
            best = (v > best) ? v : best;
        }
        last = (int)(~(unsigned)best);
    }
}

// GEMM body, 512 threads, SMEM j-tile staging (proven).
template<int C, int Cout>
__device__ __forceinline__ void dev_gemm(const float* __restrict__ f,
                                         const float* __restrict__ w,
                                         int Nk, float* __restrict__ out,
                                         bool diff, int bq, int b, float* ws) {
    constexpr int OC = Cout / 4;
    constexpr int JT = 512 / OC;
    float* tile = ws + C * Cout;
    for (int i = threadIdx.x; i < C * Cout; i += 512) {
        int c = i / Cout, o = i % Cout;
        float lo = w[o*2*C + c];
        float hi = w[o*2*C + C + c];
        ws[c*Cout + o] = diff ? (hi - lo) : lo;
    }
    int j0 = bq * JT;
    const float* fb = f + (size_t)b*C*Nk;
    for (int i = threadIdx.x; i < C * JT; i += 512) {
        int c = i / JT, jj = i % JT;
        tile[i] = fb[(size_t)c*Nk + j0 + jj];
    }
    __syncthreads();
    int jj = threadIdx.x / OC, oc = threadIdx.x % OC;
    float a0 = 0.f, a1 = 0.f, a2 = 0.f, a3 = 0.f;
#pragma unroll
    for (int c = 0; c < C; c++) {
        float fv = tile[c*JT + jj];
        float4 wv = *(const float4*)&ws[c*Cout + oc*4];
        a0 += fv * wv.x; a1 += fv * wv.y; a2 += fv * wv.z; a3 += fv * wv.w;
    }
    *(float4*)&out[((size_t)b*Nk + j0 + jj)*Cout + oc*4] = make_float4(a0, a1, a2, a3);
}

// fused input-linear + stage-1 dual GEMM, 512 threads (proven).
__device__ __forceinline__ void dev_gemmIn(const float* __restrict__ x,
                                           const float* __restrict__ w_in,
                                           const float* __restrict__ b_in,
                                           const float* __restrict__ w1,
                                           float* __restrict__ g1, float* __restrict__ h1,
                                           int r, float* ws) {
    float* wlo = ws; float* wdf = ws + 256; float* win = ws + 512; float* bin = ws + 536;
    int t = threadIdx.x;
    if (t < 256) {
        int o = t & 31, c = t >> 5;
        float lo = w1[o*16 + c];
        float hi = w1[o*16 + 8 + c];
        wlo[c*32 + o] = lo;
        wdf[c*32 + o] = hi - lo;
    }
    if (t < 24) win[t] = w_in[t];
    if (t < 8)  bin[t] = b_in[t];
    __syncthreads();
    int b = r >> 5, jb = r & 31;
    int oc = t & 7, jo = t >> 3;
    int j = jb * 64 + jo;
    float x0 = x[((size_t)b*3+0)*N0 + j];
    float x1 = x[((size_t)b*3+1)*N0 + j];
    float x2 = x[((size_t)b*3+2)*N0 + j];
    float f0[8];
#pragma unroll
    for (int o = 0; o < 8; o++)
        f0[o] = win[o*3+0]*x0 + win[o*3+1]*x1 + win[o*3+2]*x2 + bin[o];
    float g0=0.f,g1v=0.f,g2v=0.f,g3v=0.f, h0=0.f,h1v=0.f,h2v=0.f,h3v=0.f;
#pragma unroll
    for (int c = 0; c < 8; c++) {
        float fv = f0[c];
        float4 wl = *(const float4*)&wlo[c*32 + oc*4];
        float4 wd = *(const float4*)&wdf[c*32 + oc*4];
        g0 += fv*wl.x; g1v += fv*wl.y; g2v += fv*wl.z; g3v += fv*wl.w;
        h0 += fv*wd.x; h1v += fv*wd.y; h2v += fv*wd.z; h3v += fv*wd.w;
    }
    size_t o4 = ((size_t)b*N0 + j)*32 + oc*4;
    *(float4*)&g1[o4] = make_float4(g0,g1v,g2v,g3v);
    *(float4*)&h1[o4] = make_float4(h0,h1v,h2v,h3v);
}

// idx gather: dst[b,s,:] = src[b, sel[b,s], :]
__device__ __forceinline__ void dev_idx_gather(const int* __restrict__ src, int Nsrc,
                                               const int* __restrict__ sel, int S,
                                               int* __restrict__ dst, int r) {
    int i = r * 512 + threadIdx.x;
    int b = i / (S * 4);
    int rem = i % (S * 4);
    int s = rem >> 2, u = rem & 3;
    int id = sel[(size_t)b*S + s];
    const int4* sp = (const int4*)(src + ((size_t)b*Nsrc + id)*KN);
    int4* dp = (int4*)(dst + ((size_t)b*S + s)*KN);
    dp[u] = sp[u];
}

// ---------------- kernels ----------------

// megaA (512 thr): [0,32) fps1; [32,4128) knn1; [4128,4130) zero st+cnt;
// [4130,5154) gemmIn
__global__ __launch_bounds__(512) void k_megaA(const float* __restrict__ x,
                                               const float* __restrict__ w_in,
                                               const float* __restrict__ b_in,
                                               const float* __restrict__ w1,
                                               int* __restrict__ fps1,
                                               int* __restrict__ idx1,
                                               float* __restrict__ g1,
                                               float* __restrict__ h1,
                                               double* __restrict__ st,
                                               int* __restrict__ cnt) {
    __shared__ __align__(16) char sraw[33792];
    int bid = blockIdx.x;
    if (bid < 32) {
        dev_fps<N0, N1>(x, fps1, bid, sraw);
    } else if (bid < 32 + 4096) {
        int r = bid - 32;
        dev_knn(N0, x, x, N0, idx1, r & 127, r >> 7, sraw);
    } else if (bid < 32 + 4096 + 2) {
        int idx = (bid - 4128) * 512 + threadIdx.x;
        if (idx < 4 * B * 8) st[idx] = 0.0;
        if (bid == 4128 && threadIdx.x < 4 * B) cnt[threadIdx.x] = 0;
    } else {
        dev_gemmIn(x, w_in, b_in, w1, g1, h1, bid - 4130, (float*)sraw);
    }
}

// megaB (512 thr): [0,32) fps2; [32,1056) knn3; [1056,1184) idx2-gather;
// [1184,3232) g2; [3232,3744) h2
__global__ __launch_bounds__(512) void k_megaB(const float* __restrict__ cq1,
                                               const float* __restrict__ f1,
                                               const float* __restrict__ fq1,
                                               const float* __restrict__ w2,
                                               const int* __restrict__ idx1,
                                               const int* __restrict__ fps1,
                                               int* __restrict__ fps2,
                                               int* __restrict__ idx2,
                                               int* __restrict__ idx3,
                                               float* __restrict__ g2,
                                               float* __restrict__ h2) {
    __shared__ __align__(16) char sraw[33792];
    int bid = blockIdx.x;
    if (bid < 32) {
        dev_fps<N1, N2>(cq1, fps2, bid, sraw);
    } else if (bid < 1056) {
        int r = bid - 32;
        dev_knn(N1, cq1, cq1, N1, idx3, r & 31, r >> 5, sraw);
    } else if (bid < 1184) {
        dev_idx_gather(idx1, N0, fps1, N1, idx2, bid - 1056);
    } else if (bid < 3232) {
        int r = bid - 1184;
        dev_gemm<32, 64>(f1, w2, N0, g2, false, r & 63, r >> 6, (float*)sraw);
    } else {
        int r = bid - 3232;
        dev_gemm<32, 64>(fq1, w2, N1, h2, true, r & 15, r >> 4, (float*)sraw);
    }
}

// megaC (512 thr): [0,32) idx4-gather; [32,1056) g4; [1056,1312) h4
__global__ __launch_bounds__(512) void k_megaC(const float* __restrict__ f3,
                                               const float* __restrict__ fq3,
                                               const float* __restrict__ w4,
                                               const int* __restrict__ idx3,
                                               const int* __restrict__ fps2,
                                               int* __restrict__ idx4,
                                               float* __restrict__ g4,
                                               float* __restrict__ h4) {
    __shared__ __align__(16) char sraw[36864];
    int bid = blockIdx.x;
    if (bid < 32) {
        dev_idx_gather(idx3, N1, fps2, N2, idx4, bid);
    } else if (bid < 32 + 1024) {
        int r = bid - 32;
        dev_gemm<64, 128>(f3, w4, N1, g4, false, r & 31, r >> 5, (float*)sraw);
    } else {
        int r = bid - 1056;
        dev_gemm<64, 128>(fq3, w4, N2, h4, true, r & 7, r >> 3, (float*)sraw);
    }
}

// stats body: returns per-thread sums; also writes mx/mn.
template<int Cout>
__device__ __forceinline__ void dev_stats_body(const float* __restrict__ g,
                                               const float* __restrict__ h,
                                               const int* __restrict__ idx,
                                               int Nq, int Nk, int b,
                                               float* __restrict__ mx, float* __restrict__ mn,
                                               double* __restrict__ stats) {
    constexpr int OC = Cout / 4;
    __shared__ float ssum[4], ssq[4];
    if (threadIdx.x < 4) { ssum[threadIdx.x] = 0.f; ssq[threadIdx.x] = 0.f; }
    __syncthreads();
    int t = blockIdx.x * blockDim.x + threadIdx.x;
    int n = t / OC, oc = t % OC;
    float s = 0.f, ss = 0.f;
    int grp = 0;
    if (n < Nq) {
        grp = (oc * 16) / Cout;
        const int4* ib4 = (const int4*)(idx + ((size_t)b*Nq + n) * KN);
        int jj[KN];
#pragma unroll
        for (int u = 0; u < 4; u++) {
            int4 v = ib4[u];
            jj[u*4+0] = v.x; jj[u*4+1] = v.y; jj[u*4+2] = v.z; jj[u*4+3] = v.w;
        }
        float4 hv = *(const float4*)&h[((size_t)b*Nq + n)*Cout + oc*4];
        float4 m4 = make_float4(-3.4e38f, -3.4e38f, -3.4e38f, -3.4e38f);
        float4 n4 = make_float4( 3.4e38f,  3.4e38f,  3.4e38f,  3.4e38f);
#pragma unroll
        for (int k = 0; k < KN; k++) {
            float4 gv = *(const float4*)&g[((size_t)b*Nk + jj[k])*Cout + oc*4];
            float y0 = gv.x + hv.x, y1 = gv.y + hv.y, y2 = gv.z + hv.z, y3 = gv.w + hv.w;
            m4.x = fmaxf(m4.x, y0); m4.y = fmaxf(m4.y, y1);
            m4.z = fmaxf(m4.z, y2); m4.w = fmaxf(m4.w, y3);
            n4.x = fminf(n4.x, y0); n4.y = fminf(n4.y, y1);
            n4.z = fminf(n4.z, y2); n4.w = fminf(n4.w, y3);
            s  += (y0 + y1) + (y2 + y3);
            ss += (y0*y0 + y1*y1) + (y2*y2 + y3*y3);
        }
        *(float4*)&mx[((size_t)b*Nq + n)*Cout + oc*4] = m4;
        *(float4*)&mn[((size_t)b*Nq + n)*Cout + oc*4] = n4;
    }
    atomicAdd(&ssum[grp], s);
    atomicAdd(&ssq[grp], ss);
    __syncthreads();
    if (threadIdx.x < 4) {
        atomicAdd(&stats[((size_t)b*4 + threadIdx.x)*2 + 0], (double)ssum[threadIdx.x]);
        atomicAdd(&stats[((size_t)b*4 + threadIdx.x)*2 + 1], (double)ssq[threadIdx.x]);
    }
}

// last-block detection + group (mean,rstd) precompute into smem. Returns true
// for the (single) last block of batch b; smean/srstd filled for it.
__device__ __forceinline__ bool dev_last_block(double* __restrict__ stats, int* __restrict__ cnt,
                                               int b, int GX, int Nq, int Cout,
                                               float* smean, float* srstd, int* sflag) {
    __threadfence();
    if (threadIdx.x == 0) {
        int old = atomicAdd(&cnt[b], 1);
        *sflag = (old == GX - 1);
    }
    __syncthreads();
    if (!*sflag) return false;
    __threadfence();
    if (threadIdx.x < 4) {
        double su = atomicAdd(&stats[((size_t)b*4 + threadIdx.x)*2 + 0], 0.0);
        double sq = atomicAdd(&stats[((size_t)b*4 + threadIdx.x)*2 + 1], 0.0);
        double c = (double)(Cout / 4) * (double)Nq * (double)KN;
        double m = su / c;
        double vr = sq / c - m * m;
        smean[threadIdx.x] = (float)m;
        srstd[threadIdx.x] = rsqrtf((float)vr + 1e-5f);
    }
    __syncthreads();
    return true;
}

__device__ __forceinline__ float finval_fast(const float* __restrict__ mx, const float* __restrict__ mn,
                                             const float* smean, const float* srstd,
                                             const float* __restrict__ gamma, const float* __restrict__ beta,
                                             int b, int n, int o, int Nq, int C) {
    int grp = o / (C / 4);
    float ga = gamma[o];
    float sel = (ga >= 0.f) ? mx[((size_t)b*Nq + n)*C + o]
                            : mn[((size_t)b*Nq + n)*C + o];
    float v = (sel - smean[grp]) * srstd[grp] * ga + beta[o];
    return (v >= 0.f) ? v : 0.2f * v;
}

// stats + last-block finalize-full (stages 2 & 4). grid (GX, B), 128 thr.
template<int Cout>
__global__ void k_statsFin(const float* __restrict__ g, const float* __restrict__ h,
                           const int* __restrict__ idx, int Nq, int Nk,
                           float* __restrict__ mx, float* __restrict__ mn,
                           double* __restrict__ stats, int* __restrict__ cnt, int GX,
                           const float* __restrict__ gamma, const float* __restrict__ beta,
                           float* __restrict__ fout) {
    __shared__ float smean[4], srstd[4];
    __shared__ int sflag;
    int b = blockIdx.y;
    dev_stats_body<Cout>(g, h, idx, Nq, Nk, b, mx, mn, stats);
    if (!dev_last_block(stats, cnt, b, GX, Nq, Cout, smean, srstd, &sflag)) return;
    for (int i = threadIdx.x; i < Cout * Nq; i += blockDim.x) {
        int o = i / Nq, n = i % Nq;
        fout[((size_t)b*Cout + o)*Nq + n] =
            finval_fast(mx, mn, smean, srstd, gamma, beta, b, n, o, Nq, Cout);
    }
}

// stats + last-block finalize-full + sampled gather (stages 1 & 3).
template<int Cout>
__global__ void k_statsFinGather(const float* __restrict__ g, const float* __restrict__ h,
                                 const int* __restrict__ idx, int Nq, int Nk,
                                 float* __restrict__ mx, float* __restrict__ mn,
                                 double* __restrict__ stats, int* __restrict__ cnt, int GX,
                                 const float* __restrict__ gamma, const float* __restrict__ beta,
                                 float* __restrict__ fout,
                                 const float* __restrict__ srcc, const int* __restrict__ fpsi,
                                 int S, float* __restrict__ dstc, float* __restrict__ dstf) {
    __shared__ float smean[4], srstd[4];
    __shared__ int sflag;
    int b = blockIdx.y;
    dev_stats_body<Cout>(g, h, idx, Nq, Nk, b, mx, mn, stats);
    if (!dev_last_block(stats, cnt, b, GX, Nq, Cout, smean, srstd, &sflag)) return;
    for (int i = threadIdx.x; i < Cout * Nq; i += blockDim.x) {
        int o = i / Nq, n = i % Nq;
        fout[((size_t)b*Cout + o)*Nq + n] =
            finval_fast(mx, mn, smean, srstd, gamma, beta, b, n, o, Nq, Cout);
    }
    for (int i = threadIdx.x; i < (3 + Cout) * S; i += blockDim.x) {
        int c = i / S, s = i % S;
        int id = fpsi[(size_t)b*S + s];
        if (c < 3)
            dstc[((size_t)b*3 + c)*S + s] = srcc[((size_t)b*3 + c)*Nq + id];
        else
            dstf[((size_t)b*Cout + (c-3))*S + s] =
                finval_fast(mx, mn, smean, srstd, gamma, beta, b, id, c-3, Nq, Cout);
    }
}

// stage-3 dual GEMM (256 thr, proven)
template<int C, int Cout>
__global__ void k_gemm2(const float* __restrict__ f, const float* __restrict__ w,
                        int Nk, float* __restrict__ g, float* __restrict__ h) {
    constexpr int OC = Cout / 4;
    constexpr int JT = 256 / OC;
    __shared__ float ws[2 * C * Cout + C * JT];
    float* tile = ws + 2 * C * Cout;
    int b = blockIdx.y;
    for (int i = threadIdx.x; i < C * Cout; i += blockDim.x) {
        int c = i / Cout, o = i % Cout;
        float lo = w[o*2*C + c];
        float hi = w[o*2*C + C + c];
        ws[(2*c)*Cout + o]   = lo;
        ws[(2*c+1)*Cout + o] = hi - lo;
    }
    int j0 = blockIdx.x * JT;
    const float* fb = f + (size_t)b*C*Nk;
    for (int i = threadIdx.x; i < C * JT; i += blockDim.x) {
        int c = i / JT, jj = i % JT;
        tile[i] = fb[(size_t)c*Nk + j0 + jj];
    }
    __syncthreads();
    int jj = threadIdx.x / OC, oc = threadIdx.x % OC;
    float g0=0.f,g1=0.f,g2=0.f,g3=0.f, h0=0.f,h1=0.f,h2=0.f,h3=0.f;
#pragma unroll
    for (int c = 0; c < C; c++) {
        float fv = tile[c*JT + jj];
        float4 wl = *(const float4*)&ws[(2*c)*Cout + oc*4];
        float4 wd = *(const float4*)&ws[(2*c+1)*Cout + oc*4];
        g0 += fv*wl.x; g1 += fv*wl.y; g2 += fv*wl.z; g3 += fv*wl.w;
        h0 += fv*wd.x; h1 += fv*wd.y; h2 += fv*wd.z; h3 += fv*wd.w;
    }
    size_t o4 = ((size_t)b*Nk + j0 + jj)*Cout + oc*4;
    *(float4*)&g[o4] = make_float4(g0,g1,g2,g3);
    *(float4*)&h[o4] = make_float4(h0,h1,h2,h3);
}

// ---------------- launch ----------------
extern "C" void kernel_launch(void* const* d_in, const int* in_sizes, int n_in,
                              void* d_out, int out_size) {
    const float* x    = (const float*)d_in[0];
    const float* w_in = (const float*)d_in[1];
    const float* b_in = (const float*)d_in[2];
    const float* w1 = (const float*)d_in[3];
    const float* g1p = (const float*)d_in[4];
    const float* b1p = (const float*)d_in[5];
    const float* w2 = (const float*)d_in[6];
    const float* g2p = (const float*)d_in[7];
    const float* b2p = (const float*)d_in[8];
    const float* w3 = (const float*)d_in[9];
    const float* g3p = (const float*)d_in[10];
    const float* b3p = (const float*)d_in[11];
    const float* w4 = (const float*)d_in[12];
    const float* g4p = (const float*)d_in[13];
    const float* b4p = (const float*)d_in[14];

    float*  fb;  cudaGetSymbolAddress((void**)&fb,  d_fbuf);
    int*    ib;  cudaGetSymbolAddress((void**)&ib,  d_ibuf);
    double* st;  cudaGetSymbolAddress((void**)&st,  d_statsbuf);
    int*    cb;  cudaGetSymbolAddress((void**)&cb,  d_cntbuf);
    float*  out = (float*)d_out;

    float* g1  = fb + OFF_G1;  float* h1 = fb + OFF_H1;
    float* m1  = fb + OFF_M1;  float* mn1 = fb + OFF_MN1; float* f1 = fb + OFF_F1;
    float* cq1 = fb + OFF_CQ1; float* fq1 = fb + OFF_FQ1;
    float* g2  = fb + OFF_G2;  float* h2 = fb + OFF_H2;
    float* m2  = fb + OFF_M2;  float* mn2 = fb + OFF_MN2; float* f2 = fb + OFF_F2;
    float* g3  = fb + OFF_G3;  float* h3 = fb + OFF_H3;
    float* m3  = fb + OFF_M3;  float* mn3 = fb + OFF_MN3; float* f3 = fb + OFF_F3;
    float* fq3 = fb + OFF_FQ3;
    float* g4  = fb + OFF_G4;  float* h4 = fb + OFF_H4;
    float* m4  = fb + OFF_M4;  float* mn4 = fb + OFF_MN4;

    int* idx1 = ib + IOFF_IDX1; int* fps1 = ib + IOFF_FPS1;
    int* idx2 = ib + IOFF_IDX2; int* idx3 = ib + IOFF_IDX3;
    int* fps2 = ib + IOFF_FPS2; int* idx4 = ib + IOFF_IDX4;

    double* st1 = st + 0 * B * 8;
    double* st2 = st + 1 * B * 8;
    double* st3 = st + 2 * B * 8;
    double* st4 = st + 3 * B * 8;
    int* c1 = cb + 0 * B; int* c2 = cb + 1 * B;
    int* c3 = cb + 2 * B; int* c4 = cb + 3 * B;

    float* out_coor = out;                 // (B,3,128)
    float* out_f    = out + B * 3 * N2;    // (B,128,128)

    // 1: fps1 ∥ knn1 ∥ (lin+gemm1) ∥ zero(st, cnt)
    k_megaA<<<32 + 4096 + 2 + 1024, 512>>>(x, w_in, b_in, w1, fps1, idx1, g1, h1, st, cb);

    // 2: stage-1 stats + last-block fin(f1) + gather(cq1, fq1)
    k_statsFinGather<32><<<dim3(128, B), 128>>>(
        g1, h1, idx1, N0, N0, m1, mn1, st1, c1, 128, g1p, b1p, f1,
        x, fps1, N1, cq1, fq1);

    // 3: fps2 ∥ knn3 ∥ idx2-gather ∥ g2 ∥ h2
    k_megaB<<<32 + 1024 + 128 + 2048 + 512, 512>>>(cq1, f1, fq1, w2, idx1, fps1,
                                                   fps2, idx2, idx3, g2, h2);

    // 4: stage-2 stats + last-block fin(f2)
    k_statsFin<64><<<dim3(64, B), 128>>>(
        g2, h2, idx2, N1, N0, m2, mn2, st2, c2, 64, g2p, b2p, f2);

    // 5: stage-3 dual GEMM
    k_gemm2<64, 64><<<dim3(N1/16, B), 256>>>(f2, w3, N1, g3, h3);

    // 6: stage-3 stats + last-block fin(f3) + gather(out_coor, fq3)
    k_statsFinGather<64><<<dim3(64, B), 128>>>(
        g3, h3, idx3, N1, N1, m3, mn3, st3, c3, 64, g3p, b3p, f3,
        cq1, fps2, N2, out_coor, fq3);

    // 7: idx4-gather ∥ g4 ∥ h4
    k_megaC<<<32 + 1024 + 256, 512>>>(f3, fq3, w4, idx3, fps2, idx4, g4, h4);

    // 8: stage-4 stats + last-block fin -> out_f
    k_statsFin<128><<<dim3(32, B), 128>>>(
        g4, h4, idx4, N2, N1, m4, mn4, st4, c4, 32, g4p, b4p, out_f);
}

// round 17
// speedup vs baseline: 1.4035x; 1.4035x over previous
#include <cuda_runtime.h>
#include <math.h>

#define CDIV(a,b) (((a)+(b)-1)/(b))

static constexpr int B  = 32;
static constexpr int KN = 16;
static constexpr int N0 = 2048, N1 = 512, N2 = 128;

// ---------------- scratch ----------------
static constexpr size_t OFF_G1  = 0;                                  // B*N0*32
static constexpr size_t OFF_H1  = OFF_G1  + (size_t)B*N0*32;
static constexpr size_t OFF_M1  = OFF_H1  + (size_t)B*N0*32;
static constexpr size_t OFF_MN1 = OFF_M1  + (size_t)B*N0*32;
static constexpr size_t OFF_F1  = OFF_MN1 + (size_t)B*N0*32;          // B*32*N0
static constexpr size_t OFF_CQ1 = OFF_F1  + (size_t)B*32*N0;          // B*3*N1
static constexpr size_t OFF_FQ1 = OFF_CQ1 + (size_t)B*3*N1;           // B*32*N1
static constexpr size_t OFF_G2  = OFF_FQ1 + (size_t)B*32*N1;          // B*N0*64
static constexpr size_t OFF_H2  = OFF_G2  + (size_t)B*N0*64;          // B*N1*64
static constexpr size_t OFF_M2  = OFF_H2  + (size_t)B*N1*64;
static constexpr size_t OFF_MN2 = OFF_M2  + (size_t)B*N1*64;
static constexpr size_t OFF_F2  = OFF_MN2 + (size_t)B*N1*64;          // B*64*N1
static constexpr size_t OFF_G3  = OFF_F2  + (size_t)B*64*N1;
static constexpr size_t OFF_H3  = OFF_G3  + (size_t)B*N1*64;
static constexpr size_t OFF_M3  = OFF_H3  + (size_t)B*N1*64;
static constexpr size_t OFF_MN3 = OFF_M3  + (size_t)B*N1*64;
static constexpr size_t OFF_F3  = OFF_MN3 + (size_t)B*N1*64;          // B*64*N1
static constexpr size_t OFF_FQ3 = OFF_F3  + (size_t)B*64*N1;          // B*64*N2
static constexpr size_t OFF_G4  = OFF_FQ3 + (size_t)B*64*N2;          // B*N1*128
static constexpr size_t OFF_H4  = OFF_G4  + (size_t)B*N1*128;         // B*N2*128
static constexpr size_t OFF_M4  = OFF_H4  + (size_t)B*N2*128;
static constexpr size_t OFF_MN4 = OFF_M4  + (size_t)B*N2*128;
static constexpr size_t FBUF_TOTAL = OFF_MN4 + (size_t)B*N2*128;

__device__ float d_fbuf[FBUF_TOTAL];

static constexpr size_t IOFF_IDX1 = 0;
static constexpr size_t IOFF_FPS1 = IOFF_IDX1 + (size_t)B*N0*KN;
static constexpr size_t IOFF_IDX2 = IOFF_FPS1 + (size_t)B*N1;
static constexpr size_t IOFF_IDX3 = IOFF_IDX2 + (size_t)B*N1*KN;
static constexpr size_t IOFF_FPS2 = IOFF_IDX3 + (size_t)B*N1*KN;
static constexpr size_t IOFF_IDX4 = IOFF_FPS2 + (size_t)B*N2;
static constexpr size_t IBUF_TOTAL = IOFF_IDX4 + (size_t)B*N2*KN;

__device__ int d_ibuf[IBUF_TOTAL];
__device__ double d_statsbuf[4 * B * 4 * 2];   // [layer][b][group][{sum,sumsq}]

// ---------------- device helpers ----------------

// Warp-cooperative KNN, 512-thread blocks, 16 queries/block (proven R12/R14).
__device__ __forceinline__ void dev_knn(int NK, const float* __restrict__ cq,
                                        const float* __restrict__ ck,
                                        int Nq, int* __restrict__ idx_out,
                                        int qblk, int b, char* sraw) {
    float4* skey = (float4*)sraw;
    const float* ckb = ck + (size_t)b*3*NK;
    for (int j = threadIdx.x; j < NK; j += 512) {
        float kx = ckb[j], ky = ckb[NK + j], kz = ckb[2*NK + j];
        skey[j] = make_float4(-2.f*kx, -2.f*ky, -2.f*kz, kx*kx + ky*ky + kz*kz);
    }
    __syncthreads();
    int w = threadIdx.x >> 5, lane = threadIdx.x & 31;
    int q = qblk * 16 + w;
    const float* cqb = cq + (size_t)b*3*Nq;
    float qx = cqb[q], qy = cqb[Nq + q], qz = cqb[2*Nq + q];

    // seed: bitonic sort of keys 0..31 by (d, j) ascending
    float bd; int bj;
    {
        float4 kk = skey[lane];
        bd = fmaf(kk.x, qx, fmaf(kk.y, qy, fmaf(kk.z, qz, kk.w)));
        bj = lane;
#pragma unroll
        for (int k = 2; k <= 32; k <<= 1) {
#pragma unroll
            for (int s2 = k >> 1; s2 > 0; s2 >>= 1) {
                float pd = __shfl_xor_sync(0xffffffffu, bd, s2);
                int   pj = __shfl_xor_sync(0xffffffffu, bj, s2);
                bool asc    = ((lane & k)  == 0) || (k == 32);
                bool lower  = ((lane & s2) == 0);
                bool pLess  = (pd < bd) || (pd == bd && pj < bj);
                bool take   = ((asc == lower) == pLess);
                bd = take ? pd : bd;
                bj = take ? pj : bj;
            }
        }
    }
    float th = __shfl_sync(0xffffffffu, bd, 15);

    // main scan, 64 keys per iteration
    for (int j0 = 32; j0 < NK; j0 += 64) {
        float4 kkA = skey[j0 + lane];
        float dA = fmaf(kkA.x, qx, fmaf(kkA.y, qy, fmaf(kkA.z, qz, kkA.w)));
        unsigned hitsA = __ballot_sync(0xffffffffu, dA < th);
        bool hasB = (j0 + 32) < NK;
        float dB = 0.f;
        unsigned hitsB = 0;
        if (hasB) {
            float4 kkB = skey[j0 + 32 + lane];
            dB = fmaf(kkB.x, qx, fmaf(kkB.y, qy, fmaf(kkB.z, qz, kkB.w)));
            hitsB = __ballot_sync(0xffffffffu, dB < th);
        }
        while (hitsA) {
            int s = __ffs(hitsA) - 1;
            hitsA &= hitsA - 1;
            float dd = __shfl_sync(0xffffffffu, dA, s);
            if (dd < th) {
                int r = __popc(__ballot_sync(0xffffffffu, bd <= dd) & 0xFFFFu);
                float pd = __shfl_up_sync(0xffffffffu, bd, 1);
                int   pj = __shfl_up_sync(0xffffffffu, bj, 1);
                if (lane > r && lane < 16) { bd = pd; bj = pj; }
                if (lane == r)             { bd = dd; bj = j0 + s; }
                th = __shfl_sync(0xffffffffu, bd, 15);
            }
        }
        while (hitsB) {
            int s = __ffs(hitsB) - 1;
            hitsB &= hitsB - 1;
            float dd = __shfl_sync(0xffffffffu, dB, s);
            if (dd < th) {
                int r = __popc(__ballot_sync(0xffffffffu, bd <= dd) & 0xFFFFu);
                float pd = __shfl_up_sync(0xffffffffu, bd, 1);
                int   pj = __shfl_up_sync(0xffffffffu, bj, 1);
                if (lane > r && lane < 16) { bd = pd; bj = pj; }
                if (lane == r)             { bd = dd; bj = j0 + 32 + s; }
                th = __shfl_sync(0xffffffffu, bd, 15);
            }
        }
    }
    if (lane < 16) idx_out[((size_t)b*Nq + q)*KN + lane] = bj;
}

// FPS, 512 threads, one barrier/iter, packed-u64 block merge (proven).
template<int N, int S>
__device__ __forceinline__ void dev_fps(const float* __restrict__ coor,
                                        int* __restrict__ out, int b, char* sraw) {
    constexpr int BLK = 512, PPT = N / BLK, NW = BLK / 32;
    float* sx = (float*)sraw;
    float* sy = sx + N;
    float* sz = sy + N;
    unsigned long long* spk = (unsigned long long*)(sz + N);  // [2][NW]
    int t = threadIdx.x, lane = t & 31, w = t >> 5;
    const float* cb = coor + (size_t)b*3*N;

    float px[PPT], py[PPT], pz[PPT], dist[PPT];
#pragma unroll
    for (int p = 0; p < PPT; p++) {
        int i = t + p * BLK;
        float vx = cb[i], vy = cb[N + i], vz = cb[2*N + i];
        px[p] = vx; py[p] = vy; pz[p] = vz;
        sx[i] = vx; sy[i] = vy; sz[i] = vz;
        dist[p] = 1e10f;
    }
    __syncthreads();

    int last = 0;
    for (int s = 0; s < S; s++) {
        if (t == 0) out[(size_t)b*S + s] = last;
        float cx = sx[last], cy = sy[last], cz = sz[last];
        float bv = -1.0f; int bidx = 0;
#pragma unroll
        for (int p = 0; p < PPT; p++) {
            float dx = px[p]-cx, dy = py[p]-cy, dz = pz[p]-cz;
            float d = dx*dx + dy*dy + dz*dz;
            float nd = fminf(dist[p], d);
            dist[p] = nd;
            if (nd > bv) { bv = nd; bidx = t + p * BLK; }
        }
        unsigned bits = __float_as_uint(fmaxf(bv, 0.0f));
        unsigned m  = __reduce_max_sync(0xffffffffu, bits);
        unsigned ci = (bits == m) ? (unsigned)bidx : 0xffffffffu;
        unsigned mi = __reduce_min_sync(0xffffffffu, ci);
        int buf = (s & 1) * NW;
        if (lane == 0)
            spk[buf + w] = ((unsigned long long)m << 32) | (unsigned)(~mi);
        __syncthreads();
        unsigned long long best = spk[buf + 0];
#pragma unroll
        for (int i2 = 1; i2 < NW; i2++) {
            unsigned long long v = spk[buf + i2];
            best = (v > best) ? v : best;
        }
        last = (int)(~(unsigned)best);
    }
}

// GEMM body, 512 threads, SMEM j-tile staging. Block covers JT = 512/OC j's.
template<int C, int Cout>
__device__ __forceinline__ void dev_gemm(const float* __restrict__ f,
                                         const float* __restrict__ w,
                                         int Nk, float* __restrict__ out,
                                         bool diff, int bq, int b, float* ws) {
    constexpr int OC = Cout / 4;
    constexpr int JT = 512 / OC;
    float* tile = ws + C * Cout;          // [C][JT]
    for (int i = threadIdx.x; i < C * Cout; i += 512) {
        int c = i / Cout, o = i % Cout;
        float lo = w[o*2*C + c];
        float hi = w[o*2*C + C + c];
        ws[c*Cout + o] = diff ? (hi - lo) : lo;
    }
    int j0 = bq * JT;
    const float* fb = f + (size_t)b*C*Nk;
    for (int i = threadIdx.x; i < C * JT; i += 512) {
        int c = i / JT, jj = i % JT;
        tile[i] = fb[(size_t)c*Nk + j0 + jj];
    }
    __syncthreads();
    int jj = threadIdx.x / OC, oc = threadIdx.x % OC;
    float a0 = 0.f, a1 = 0.f, a2 = 0.f, a3 = 0.f;
#pragma unroll
    for (int c = 0; c < C; c++) {
        float fv = tile[c*JT + jj];
        float4 wv = *(const float4*)&ws[c*Cout + oc*4];
        a0 += fv * wv.x; a1 += fv * wv.y; a2 += fv * wv.z; a3 += fv * wv.w;
    }
    *(float4*)&out[((size_t)b*Nk + j0 + jj)*Cout + oc*4] = make_float4(a0, a1, a2, a3);
}

// fused input-linear + stage-1 dual GEMM, 512 threads (proven).
__device__ __forceinline__ void dev_gemmIn(const float* __restrict__ x,
                                           const float* __restrict__ w_in,
                                           const float* __restrict__ b_in,
                                           const float* __restrict__ w1,
                                           float* __restrict__ g1, float* __restrict__ h1,
                                           int r, float* ws) {
    float* wlo = ws; float* wdf = ws + 256; float* win = ws + 512; float* bin = ws + 536;
    int t = threadIdx.x;
    if (t < 256) {
        int o = t & 31, c = t >> 5;
        float lo = w1[o*16 + c];
        float hi = w1[o*16 + 8 + c];
        wlo[c*32 + o] = lo;
        wdf[c*32 + o] = hi - lo;
    }
    if (t < 24) win[t] = w_in[t];
    if (t < 8)  bin[t] = b_in[t];
    __syncthreads();
    int b = r >> 5, jb = r & 31;
    int oc = t & 7, jo = t >> 3;
    int j = jb * 64 + jo;
    float x0 = x[((size_t)b*3+0)*N0 + j];
    float x1 = x[((size_t)b*3+1)*N0 + j];
    float x2 = x[((size_t)b*3+2)*N0 + j];
    float f0[8];
#pragma unroll
    for (int o = 0; o < 8; o++)
        f0[o] = win[o*3+0]*x0 + win[o*3+1]*x1 + win[o*3+2]*x2 + bin[o];
    float g0=0.f,g1v=0.f,g2v=0.f,g3v=0.f, h0=0.f,h1v=0.f,h2v=0.f,h3v=0.f;
#pragma unroll
    for (int c = 0; c < 8; c++) {
        float fv = f0[c];
        float4 wl = *(const float4*)&wlo[c*32 + oc*4];
        float4 wd = *(const float4*)&wdf[c*32 + oc*4];
        g0 += fv*wl.x; g1v += fv*wl.y; g2v += fv*wl.z; g3v += fv*wl.w;
        h0 += fv*wd.x; h1v += fv*wd.y; h2v += fv*wd.z; h3v += fv*wd.w;
    }
    size_t o4 = ((size_t)b*N0 + j)*32 + oc*4;
    *(float4*)&g1[o4] = make_float4(g0,g1v,g2v,g3v);
    *(float4*)&h1[o4] = make_float4(h0,h1v,h2v,h3v);
}

// idx gather: dst[b,s,:] = src[b, sel[b,s], :]  (one int4 per thread, KN=16)
__device__ __forceinline__ void dev_idx_gather(const int* __restrict__ src, int Nsrc,
                                               const int* __restrict__ sel, int S,
                                               int* __restrict__ dst, int r) {
    int i = r * 512 + threadIdx.x;            // global int4 index
    int b = i / (S * 4);
    int rem = i % (S * 4);
    int s = rem >> 2, u = rem & 3;
    int id = sel[(size_t)b*S + s];
    const int4* sp = (const int4*)(src + ((size_t)b*Nsrc + id)*KN);
    int4* dp = (int4*)(dst + ((size_t)b*S + s)*KN);
    dp[u] = sp[u];
}

// finalize value for one (b,n,o)
__device__ __forceinline__ float finval(const float* __restrict__ mx, const float* __restrict__ mn,
                                        const double* __restrict__ st,
                                        const float* __restrict__ gamma, const float* __restrict__ beta,
                                        int b, int n, int o, int Nq, int C) {
    int grp = o / (C / 4);
    double cnt = (double)(C / 4) * (double)Nq * (double)KN;
    double su = st[((size_t)b*4 + grp)*2 + 0];
    double sq = st[((size_t)b*4 + grp)*2 + 1];
    double m  = su / cnt;
    double vr = sq / cnt - m * m;
    float mean = (float)m;
    float rstd = rsqrtf((float)vr + 1e-5f);
    float ga = gamma[o], be = beta[o];
    float sel = (ga >= 0.f) ? mx[((size_t)b*Nq + n)*C + o]
                            : mn[((size_t)b*Nq + n)*C + o];
    float v = (sel - mean) * rstd * ga + be;
    return (v >= 0.f) ? v : 0.2f * v;
}

// ---------------- kernels ----------------

// megaA (512 thr): [0,32) fps1; [32,4128) knn1 (16q/blk); [4128,4130) zero;
// [4130,5154) gemmIn
__global__ __launch_bounds__(512) void k_megaA(const float* __restrict__ x,
                                               const float* __restrict__ w_in,
                                               const float* __restrict__ b_in,
                                               const float* __restrict__ w1,
                                               int* __restrict__ fps1,
                                               int* __restrict__ idx1,
                                               float* __restrict__ g1,
                                               float* __restrict__ h1,
                                               double* __restrict__ st) {
    __shared__ __align__(16) char sraw[33792];
    int bid = blockIdx.x;
    if (bid < 32) {
        dev_fps<N0, N1>(x, fps1, bid, sraw);
    } else if (bid < 32 + 4096) {
        int r = bid - 32;
        dev_knn(N0, x, x, N0, idx1, r & 127, r >> 7, sraw);
    } else if (bid < 32 + 4096 + 2) {
        int idx = (bid - 4128) * 512 + threadIdx.x;
        if (idx < 4 * B * 8) st[idx] = 0.0;
    } else {
        dev_gemmIn(x, w_in, b_in, w1, g1, h1, bid - 4130, (float*)sraw);
    }
}

// megaB (512 thr): [0,32) fps2; [32,1056) knn3; [1056,1184) idx2 = gather(idx1, fps1);
// [1184,3232) g2; [3232,3744) h2
__global__ __launch_bounds__(512) void k_megaB(const float* __restrict__ cq1,
                                               const float* __restrict__ f1,
                                               const float* __restrict__ fq1,
                                               const float* __restrict__ w2,
                                               const int* __restrict__ idx1,
                                               const int* __restrict__ fps1,
                                               int* __restrict__ fps2,
                                               int* __restrict__ idx2,
                                               int* __restrict__ idx3,
                                               float* __restrict__ g2,
                                               float* __restrict__ h2) {
    __shared__ __align__(16) char sraw[33792];
    int bid = blockIdx.x;
    if (bid < 32) {
        dev_fps<N1, N2>(cq1, fps2, bid, sraw);
    } else if (bid < 1056) {
        int r = bid - 32;                     // 32 qblks per batch
        dev_knn(N1, cq1, cq1, N1, idx3, r & 31, r >> 5, sraw);
    } else if (bid < 1184) {
        dev_idx_gather(idx1, N0, fps1, N1, idx2, bid - 1056);   // B*N1*4 int4 = 128 blks
    } else if (bid < 3232) {
        int r = bid - 1184;                   // 64 blocks/batch (JT=32)
        dev_gemm<32, 64>(f1, w2, N0, g2, false, r & 63, r >> 6, (float*)sraw);
    } else {
        int r = bid - 3232;                   // 16 blocks/batch
        dev_gemm<32, 64>(fq1, w2, N1, h2, true, r & 15, r >> 4, (float*)sraw);
    }
}

// megaC (512 thr): [0,32) idx4 = gather(idx3, fps2); [32,1056) g4; [1056,1312) h4
// smem: g4 needs (64*128 + 64*16)*4 = 36864 B
__global__ __launch_bounds__(512) void k_megaC(const float* __restrict__ f3,
                                               const float* __restrict__ fq3,
                                               const float* __restrict__ w4,
                                               const int* __restrict__ idx3,
                                               const int* __restrict__ fps2,
                                               int* __restrict__ idx4,
                                               float* __restrict__ g4,
                                               float* __restrict__ h4) {
    __shared__ __align__(16) char sraw[36864];
    int bid = blockIdx.x;
    if (bid < 32) {
        dev_idx_gather(idx3, N1, fps2, N2, idx4, bid);          // B*N2*4 int4 = 32 blks
    } else if (bid < 32 + 1024) {
        int r = bid - 32;                     // 32 blocks/batch (JT=16)
        dev_gemm<64, 128>(f3, w4, N1, g4, false, r & 31, r >> 5, (float*)sraw);
    } else {
        int r = bid - 1056;                   // 8 blocks/batch
        dev_gemm<64, 128>(fq3, w4, N2, h4, true, r & 7, r >> 3, (float*)sraw);
    }
}

// fused stats+max (proven)
template<int Cout>
__global__ void k_stats_max(const float* __restrict__ g, const float* __restrict__ h,
                            const int* __restrict__ idx, int Nq, int Nk,
                            float* __restrict__ mx, float* __restrict__ mn,
                            double* __restrict__ stats) {
    constexpr int OC = Cout / 4;
    __shared__ float ssum[4], ssq[4];
    int b = blockIdx.y;
    if (threadIdx.x < 4) { ssum[threadIdx.x] = 0.f; ssq[threadIdx.x] = 0.f; }
    __syncthreads();
    int t = blockIdx.x * blockDim.x + threadIdx.x;
    int n = t / OC, oc = t % OC;
    float s = 0.f, ss = 0.f;
    int grp = 0;
    if (n < Nq) {
        grp = (oc * 16) / Cout;
        const int4* ib4 = (const int4*)(idx + ((size_t)b*Nq + n) * KN);
        int jj[KN];
#pragma unroll
        for (int u = 0; u < 4; u++) {
            int4 v = ib4[u];
            jj[u*4+0] = v.x; jj[u*4+1] = v.y; jj[u*4+2] = v.z; jj[u*4+3] = v.w;
        }
        float4 hv = *(const float4*)&h[((size_t)b*Nq + n)*Cout + oc*4];
        float4 m4 = make_float4(-3.4e38f, -3.4e38f, -3.4e38f, -3.4e38f);
        float4 n4 = make_float4( 3.4e38f,  3.4e38f,  3.4e38f,  3.4e38f);
#pragma unroll
        for (int k = 0; k < KN; k++) {
            float4 gv = *(const float4*)&g[((size_t)b*Nk + jj[k])*Cout + oc*4];
            float y0 = gv.x + hv.x, y1 = gv.y + hv.y, y2 = gv.z + hv.z, y3 = gv.w + hv.w;
            m4.x = fmaxf(m4.x, y0); m4.y = fmaxf(m4.y, y1);
            m4.z = fmaxf(m4.z, y2); m4.w = fmaxf(m4.w, y3);
            n4.x = fminf(n4.x, y0); n4.y = fminf(n4.y, y1);
            n4.z = fminf(n4.z, y2); n4.w = fminf(n4.w, y3);
            s  += (y0 + y1) + (y2 + y3);
            ss += (y0*y0 + y1*y1) + (y2*y2 + y3*y3);
        }
        *(float4*)&mx[((size_t)b*Nq + n)*Cout + oc*4] = m4;
        *(float4*)&mn[((size_t)b*Nq + n)*Cout + oc*4] = n4;
    }
    atomicAdd(&ssum[grp], s);
    atomicAdd(&ssq[grp], ss);
    __syncthreads();
    if (threadIdx.x < 4) {
        atomicAdd(&stats[((size_t)b*4 + threadIdx.x)*2 + 0], (double)ssum[threadIdx.x]);
        atomicAdd(&stats[((size_t)b*4 + threadIdx.x)*2 + 1], (double)ssq[threadIdx.x]);
    }
}

// finalize full feature map
template<int Cout>
__global__ void k_fin(const float* __restrict__ mx, const float* __restrict__ mn,
                      const double* __restrict__ stats,
                      const float* __restrict__ gamma, const float* __restrict__ beta,
                      int Nq, float* __restrict__ fout) {
    int b = blockIdx.y;
    int t = blockIdx.x * blockDim.x + threadIdx.x;
    if (t >= Cout * Nq) return;
    int o = t / Nq, n = t % Nq;
    fout[((size_t)b*Cout + o)*Nq + n] = finval(mx, mn, stats, gamma, beta, b, n, o, Nq, Cout);
}

// finalize full + gather sampled
template<int Cout, int FB>
__global__ void k_finGather(const float* __restrict__ mx, const float* __restrict__ mn,
                            const double* __restrict__ stats,
                            const float* __restrict__ gamma, const float* __restrict__ beta,
                            int Nq, float* __restrict__ fout,
                            const float* __restrict__ srcc, const int* __restrict__ fpsi,
                            int S, float* __restrict__ dstc, float* __restrict__ dstf) {
    int b = blockIdx.y;
    if (blockIdx.x < FB) {
        int t = blockIdx.x * blockDim.x + threadIdx.x;
        if (t >= Cout * Nq) return;
        int o = t / Nq, n = t % Nq;
        fout[((size_t)b*Cout + o)*Nq + n] = finval(mx, mn, stats, gamma, beta, b, n, o, Nq, Cout);
    } else {
        int t = (blockIdx.x - FB) * blockDim.x + threadIdx.x;
        if (t >= (3 + Cout) * S) return;
        int c = t / S, s = t % S;
        int id = fpsi[(size_t)b*S + s];
        if (c < 3)
            dstc[((size_t)b*3 + c)*S + s] = srcc[((size_t)b*3 + c)*Nq + id];
        else
            dstf[((size_t)b*Cout + (c-3))*S + s] =
                finval(mx, mn, stats, gamma, beta, b, id, c-3, Nq, Cout);
    }
}

// stage-3 dual GEMM (256 thr, proven)
template<int C, int Cout>
__global__ void k_gemm2(const float* __restrict__ f, const float* __restrict__ w,
                        int Nk, float* __restrict__ g, float* __restrict__ h) {
    constexpr int OC = Cout / 4;
    constexpr int JT = 256 / OC;
    __shared__ float ws[2 * C * Cout + C * JT];
    float* tile = ws + 2 * C * Cout;
    int b = blockIdx.y;
    for (int i = threadIdx.x; i < C * Cout; i += blockDim.x) {
        int c = i / Cout, o = i % Cout;
        float lo = w[o*2*C + c];
        float hi = w[o*2*C + C + c];
        ws[(2*c)*Cout + o]   = lo;
        ws[(2*c+1)*Cout + o] = hi - lo;
    }
    int j0 = blockIdx.x * JT;
    const float* fb = f + (size_t)b*C*Nk;
    for (int i = threadIdx.x; i < C * JT; i += blockDim.x) {
        int c = i / JT, jj = i % JT;
        tile[i] = fb[(size_t)c*Nk + j0 + jj];
    }
    __syncthreads();
    int jj = threadIdx.x / OC, oc = threadIdx.x % OC;
    float g0=0.f,g1=0.f,g2=0.f,g3=0.f, h0=0.f,h1=0.f,h2=0.f,h3=0.f;
#pragma unroll
    for (int c = 0; c < C; c++) {
        float fv = tile[c*JT + jj];
        float4 wl = *(const float4*)&ws[(2*c)*Cout + oc*4];
        float4 wd = *(const float4*)&ws[(2*c+1)*Cout + oc*4];
        g0 += fv*wl.x; g1 += fv*wl.y; g2 += fv*wl.z; g3 += fv*wl.w;
        h0 += fv*wd.x; h1 += fv*wd.y; h2 += fv*wd.z; h3 += fv*wd.w;
    }
    size_t o4 = ((size_t)b*Nk + j0 + jj)*Cout + oc*4;
    *(float4*)&g[o4] = make_float4(g0,g1,g2,g3);
    *(float4*)&h[o4] = make_float4(h0,h1,h2,h3);
}

// ---------------- launch ----------------
extern "C" void kernel_launch(void* const* d_in, const int* in_sizes, int n_in,
                              void* d_out, int out_size) {
    const float* x    = (const float*)d_in[0];
    const float* w_in = (const float*)d_in[1];
    const float* b_in = (const float*)d_in[2];
    const float* w1 = (const float*)d_in[3];
    const float* g1p = (const float*)d_in[4];
    const float* b1p = (const float*)d_in[5];
    const float* w2 = (const float*)d_in[6];
    const float* g2p = (const float*)d_in[7];
    const float* b2p = (const float*)d_in[8];
    const float* w3 = (const float*)d_in[9];
    const float* g3p = (const float*)d_in[10];
    const float* b3p = (const float*)d_in[11];
    const float* w4 = (const float*)d_in[12];
    const float* g4p = (const float*)d_in[13];
    const float* b4p = (const float*)d_in[14];

    float*  fb;  cudaGetSymbolAddress((void**)&fb,  d_fbuf);
    int*    ib;  cudaGetSymbolAddress((void**)&ib,  d_ibuf);
    double* st;  cudaGetSymbolAddress((void**)&st,  d_statsbuf);
    float*  out = (float*)d_out;

    float* g1  = fb + OFF_G1;  float* h1 = fb + OFF_H1;
    float* m1  = fb + OFF_M1;  float* mn1 = fb + OFF_MN1; float* f1 = fb + OFF_F1;
    float* cq1 = fb + OFF_CQ1; float* fq1 = fb + OFF_FQ1;
    float* g2  = fb + OFF_G2;  float* h2 = fb + OFF_H2;
    float* m2  = fb + OFF_M2;  float* mn2 = fb + OFF_MN2; float* f2 = fb + OFF_F2;
    float* g3  = fb + OFF_G3;  float* h3 = fb + OFF_H3;
    float* m3  = fb + OFF_M3;  float* mn3 = fb + OFF_MN3; float* f3 = fb + OFF_F3;
    float* fq3 = fb + OFF_FQ3;
    float* g4  = fb + OFF_G4;  float* h4 = fb + OFF_H4;
    float* m4  = fb + OFF_M4;  float* mn4 = fb + OFF_MN4;

    int* idx1 = ib + IOFF_IDX1; int* fps1 = ib + IOFF_FPS1;
    int* idx2 = ib + IOFF_IDX2; int* idx3 = ib + IOFF_IDX3;
    int* fps2 = ib + IOFF_FPS2; int* idx4 = ib + IOFF_IDX4;

    double* st1 = st + 0 * B * 8;
    double* st2 = st + 1 * B * 8;
    double* st3 = st + 2 * B * 8;
    double* st4 = st + 3 * B * 8;

    float* out_coor = out;                 // (B,3,128)
    float* out_f    = out + B * 3 * N2;    // (B,128,128)

    // 1: fps1 ∥ knn1 ∥ (lin+gemm1) ∥ stats zeroing
    k_megaA<<<32 + 4096 + 2 + 1024, 512>>>(x, w_in, b_in, w1, fps1, idx1, g1, h1, st);

    // 2-3: stage-1 stats, finalize + gather
    k_stats_max<32><<<dim3(CDIV(N0*8, 128), B), 128>>>(g1, h1, idx1, N0, N0, m1, mn1, st1);
    k_finGather<32, 256><<<dim3(256 + CDIV(35*N1, 256), B), 256>>>(
        m1, mn1, st1, g1p, b1p, N0, f1, x, fps1, N1, cq1, fq1);

    // 4: fps2 ∥ knn3 ∥ idx2-gather ∥ g2 ∥ h2   (knn2 replaced by gather of idx1)
    k_megaB<<<32 + 1024 + 128 + 2048 + 512, 512>>>(cq1, f1, fq1, w2, idx1, fps1,
                                                   fps2, idx2, idx3, g2, h2);

    // 5-6: stage-2 stats + finalize
    k_stats_max<64><<<dim3(CDIV(N1*16, 128), B), 128>>>(g2, h2, idx2, N1, N0, m2, mn2, st2);
    k_fin<64><<<dim3(CDIV(64*N1, 256), B), 256>>>(m2, mn2, st2, g2p, b2p, N1, f2);

    // 7-9: stage 3
    k_gemm2<64, 64><<<dim3(N1/16, B), 256>>>(f2, w3, N1, g3, h3);
    k_stats_max<64><<<dim3(CDIV(N1*16, 128), B), 128>>>(g3, h3, idx3, N1, N1, m3, mn3, st3);
    k_finGather<64, 128><<<dim3(128 + CDIV(67*N2, 256), B), 256>>>(
        m3, mn3, st3, g3p, b3p, N1, f3, cq1, fps2, N2, out_coor, fq3);

    // 10-12: stage 4 (knn4 replaced by gather of idx3)
    k_megaC<<<32 + 1024 + 256, 512>>>(f3, fq3, w4, idx3, fps2, idx4, g4, h4);
    k_stats_max<128><<<dim3(CDIV(N2*32, 128), B), 128>>>(g4, h4, idx4, N2, N1, m4, mn4, st4);
    k_fin<128><<<dim3(CDIV(128*N2, 256), B), 256>>>(m4, mn4, st4, g4p, b4p, N2, out_f);
}